// round 15
// baseline (speedup 1.0000x reference)
#include <cuda_runtime.h>
#include <cstdint>

#define N_NODES 50000
#define N_EDGES 800000
#define HID     256
#define EMB     128
#define IN_F    10
#define BN_EPS  1e-5f
#define SCAN_BLOCKS ((N_NODES + 1023) / 1024)   // 49

// ---------------- scratch (static device globals; no allocation) ------------
__device__ float g_bufA[N_NODES * HID];
__device__ float g_bufB[N_NODES * HID];   // agg (gather target, tf32-rounded)
__device__ float g_bufC[N_NODES * HID];
__device__ float g_rcnt[N_NODES];
__device__ int   g_deg[N_NODES];
__device__ int   g_rowstart[N_NODES + 1];
__device__ int   g_cursor[N_NODES];
__device__ int   g_csrsrc[N_EDGES];
__device__ int   g_bsum[SCAN_BLOCKS];
__device__ float g_stats[2 * HID];
__device__ float g_scale[HID];
__device__ float g_shift[HID];
__device__ float g_wtf[4 * 65536 + 2 * 32768];  // tf32-rounded weights

__device__ __forceinline__ float to_tf32(float x) {
    float y;
    asm("cvt.rna.tf32.f32 %0, %1;" : "=f"(y) : "f"(x));
    return y;
}

#define CP_ASYNC16(dst_u32, src_ptr) \
    asm volatile("cp.async.ca.shared.global [%0], [%1], 16;" \
                 :: "r"(dst_u32), "l"(src_ptr) : "memory")
#define CP_COMMIT() asm volatile("cp.async.commit_group;" ::: "memory")
#define CP_WAIT(n)  asm volatile("cp.async.wait_group %0;" :: "n"(n) : "memory")

// ---------------- CSR construction -----------------------------------------
__global__ void zero_init(int* __restrict__ deg, int* __restrict__ rowstart) {
    int i = blockIdx.x * blockDim.x + threadIdx.x;
    if (i < N_NODES) deg[i] = 0;
    if (i < 2 * HID) g_stats[i] = 0.f;
    if (i == 0) rowstart[N_NODES] = N_EDGES;
}

__global__ void count_deg(const int* __restrict__ ei, int* __restrict__ deg) {
    int e = blockIdx.x * blockDim.x + threadIdx.x;
    if (e < N_EDGES) atomicAdd(deg + ei[N_EDGES + e], 1);
}

__global__ __launch_bounds__(256) void block_sums(const int* __restrict__ deg,
                                                  int* __restrict__ bsum) {
    __shared__ int ws[8];
    int t = threadIdx.x;
    int base = blockIdx.x * 1024 + t * 4;
    int s = 0;
#pragma unroll
    for (int k = 0; k < 4; k++) {
        int idx = base + k;
        if (idx < N_NODES) s += deg[idx];
    }
#pragma unroll
    for (int off = 16; off; off >>= 1) s += __shfl_down_sync(0xffffffffu, s, off);
    if ((t & 31) == 0) ws[t >> 5] = s;
    __syncthreads();
    if (t < 8) {
        int v = ws[t];
#pragma unroll
        for (int off = 4; off; off >>= 1) v += __shfl_down_sync(0xffu, v, off);
        if (t == 0) bsum[blockIdx.x] = v;
    }
}

__global__ __launch_bounds__(256) void scan_emit(const int* __restrict__ deg,
                                                 const int* __restrict__ bsum,
                                                 int* __restrict__ rowstart,
                                                 int* __restrict__ cursor,
                                                 float* __restrict__ rcnt) {
    __shared__ int s_part[2];
    __shared__ int warpsum[8];
    int t = threadIdx.x;
    int b = blockIdx.x;
    int lane = t & 31, wid = t >> 5;

    if (t < 64) {
        int v = (t < b) ? bsum[t] : 0;
#pragma unroll
        for (int off = 16; off; off >>= 1) v += __shfl_down_sync(0xffffffffu, v, off);
        if (lane == 0) s_part[wid] = v;
    }

    int base = b * 1024 + t * 4;
    int d[4];
    int tsum = 0;
#pragma unroll
    for (int k = 0; k < 4; k++) {
        int idx = base + k;
        d[k] = (idx < N_NODES) ? deg[idx] : 0;
        tsum += d[k];
    }
    int incl = tsum;
#pragma unroll
    for (int off = 1; off < 32; off <<= 1) {
        int v = __shfl_up_sync(0xffffffffu, incl, off);
        if (lane >= off) incl += v;
    }
    if (lane == 31) warpsum[wid] = incl;
    __syncthreads();
    if (t < 8) {
        int v = warpsum[t];
#pragma unroll
        for (int off = 1; off < 8; off <<= 1) {
            int u = __shfl_up_sync(0xffu, v, off);
            if (t >= off) v += u;
        }
        warpsum[t] = v;
    }
    __syncthreads();

    int run = (s_part[0] + s_part[1]) + (incl - tsum) + (wid ? warpsum[wid - 1] : 0);
#pragma unroll
    for (int k = 0; k < 4; k++) {
        int idx = base + k;
        if (idx < N_NODES) {
            rowstart[idx] = run;
            cursor[idx] = run;
            rcnt[idx] = 1.0f / fmaxf((float)d[k], 1.0f);
            run += d[k];
        }
    }
}

__global__ void fill_csr(const int* __restrict__ ei, int* __restrict__ cursor,
                         int* __restrict__ csrsrc) {
    int e = blockIdx.x * blockDim.x + threadIdx.x;
    if (e < N_EDGES) {
        int dst = ei[N_EDGES + e];
        int p = atomicAdd(cursor + dst, 1);
        csrsrc[p] = ei[e];
    }
}

// ---------------- weight pre-rounding (fp32 -> tf32 values) ------------------
__global__ void round_weights(const float* __restrict__ w1, const float* __restrict__ w2,
                              const float* __restrict__ w3, const float* __restrict__ w4,
                              const float* __restrict__ w5, const float* __restrict__ w6) {
    int i = blockIdx.x * blockDim.x + threadIdx.x;  // < 327680
    float v;
    if (i < 262144) {
        int seg = i >> 16, off = i & 65535;
        const float* s = (seg == 0) ? w1 : (seg == 1) ? w2 : (seg == 2) ? w3 : w4;
        v = s[off];
    } else {
        int j = i - 262144;
        v = (j < 32768) ? w5[j] : w6[j - 32768];
    }
    g_wtf[i] = to_tf32(v);
}

// ---------------- input projection (+ fused column stats), 64 rows/block ----
__global__ __launch_bounds__(256) void input_proj(const float* __restrict__ x,
                                                  const float* __restrict__ w,
                                                  const float* __restrict__ b,
                                                  float* __restrict__ out) {
    __shared__ float ws[IN_F * HID];
    __shared__ float xs[64 * IN_F];
    int t = threadIdx.x;
    for (int i = t; i < IN_F * HID; i += 256) ws[i] = w[i];
    int r0 = blockIdx.x * 64;
    int nr = min(64, N_NODES - r0);
    for (int i = t; i < nr * IN_F; i += 256) xs[i] = x[(size_t)r0 * IN_F + i];
    __syncthreads();
    float bb = b[t];
    float s = 0.f, s2 = 0.f;
    for (int r = 0; r < nr; r++) {
        float v = bb;
#pragma unroll
        for (int k = 0; k < IN_F; k++) v += xs[r * IN_F + k] * ws[k * HID + t];
        out[(size_t)(r0 + r) * HID + t] = v;
        s += v; s2 += v * v;
    }
    atomicAdd(&g_stats[t], s);
    atomicAdd(&g_stats[HID + t], s2);
}

// ---------------- BatchNorm params (also re-zeroes stats) --------------------
__global__ void bn_finalize(const float* __restrict__ g, const float* __restrict__ be) {
    int c = threadIdx.x;
    float mu  = g_stats[c] * (1.0f / N_NODES);
    float var = g_stats[HID + c] * (1.0f / N_NODES) - mu * mu;
    float sc  = g[c] * rsqrtf(var + BN_EPS);
    g_scale[c] = sc;
    g_shift[c] = be[c] - mu * sc;
    g_stats[c] = 0.f;
    g_stats[HID + c] = 0.f;
}

// ---------------- aggregation: gather-mean of relu(bn(raw)), tf32 output -----
__global__ __launch_bounds__(256) void agg_gather_bn(const int* __restrict__ rowstart,
                                                     const int* __restrict__ csrsrc,
                                                     const float* __restrict__ rcnt,
                                                     const float* __restrict__ raw,
                                                     float* __restrict__ agg) {
    int node = blockIdx.x * 4 + (threadIdx.x >> 6);
    int c = (threadIdx.x & 63) * 4;
    float4 sc = *(const float4*)(g_scale + c);
    float4 sh = *(const float4*)(g_shift + c);
    int j = rowstart[node];
    int e = rowstart[node + 1];
    float4 acc = make_float4(0.f, 0.f, 0.f, 0.f);
    for (; j + 4 <= e; j += 4) {
        int s0 = __ldg(csrsrc + j);
        int s1 = __ldg(csrsrc + j + 1);
        int s2 = __ldg(csrsrc + j + 2);
        int s3 = __ldg(csrsrc + j + 3);
        float4 v0 = *(const float4*)(raw + (size_t)s0 * HID + c);
        float4 v1 = *(const float4*)(raw + (size_t)s1 * HID + c);
        float4 v2 = *(const float4*)(raw + (size_t)s2 * HID + c);
        float4 v3 = *(const float4*)(raw + (size_t)s3 * HID + c);
        acc.x += fmaxf(v0.x * sc.x + sh.x, 0.f) + fmaxf(v1.x * sc.x + sh.x, 0.f)
               + fmaxf(v2.x * sc.x + sh.x, 0.f) + fmaxf(v3.x * sc.x + sh.x, 0.f);
        acc.y += fmaxf(v0.y * sc.y + sh.y, 0.f) + fmaxf(v1.y * sc.y + sh.y, 0.f)
               + fmaxf(v2.y * sc.y + sh.y, 0.f) + fmaxf(v3.y * sc.y + sh.y, 0.f);
        acc.z += fmaxf(v0.z * sc.z + sh.z, 0.f) + fmaxf(v1.z * sc.z + sh.z, 0.f)
               + fmaxf(v2.z * sc.z + sh.z, 0.f) + fmaxf(v3.z * sc.z + sh.z, 0.f);
        acc.w += fmaxf(v0.w * sc.w + sh.w, 0.f) + fmaxf(v1.w * sc.w + sh.w, 0.f)
               + fmaxf(v2.w * sc.w + sh.w, 0.f) + fmaxf(v3.w * sc.w + sh.w, 0.f);
    }
    for (; j < e; j++) {
        int s0 = __ldg(csrsrc + j);
        float4 v0 = *(const float4*)(raw + (size_t)s0 * HID + c);
        acc.x += fmaxf(v0.x * sc.x + sh.x, 0.f);
        acc.y += fmaxf(v0.y * sc.y + sh.y, 0.f);
        acc.z += fmaxf(v0.z * sc.z + sh.z, 0.f);
        acc.w += fmaxf(v0.w * sc.w + sh.w, 0.f);
    }
    float r = rcnt[node];
    float4 o;
    o.x = to_tf32(acc.x * r); o.y = to_tf32(acc.y * r);
    o.z = to_tf32(acc.z * r); o.w = to_tf32(acc.w * r);
    *(float4*)(agg + (size_t)node * HID + c) = o;
}

// ---------------- TF32 mma.sync dual GEMM (96-M tile, occupancy 3) -----------
// C = A1tf @ W1tf + relu(bn(A2raw)) @ W2tf + bias.
// Tile 96(M) x 128(N); 8 warps as 2(m) x 4(n), warp tile 48x32; acc 48/thread.
__device__ __forceinline__ void mma8(float* c, const uint32_t* a, const uint32_t* b) {
    asm volatile(
        "mma.sync.aligned.m16n8k8.row.col.f32.tf32.tf32.f32 "
        "{%0,%1,%2,%3}, {%4,%5,%6,%7}, {%8,%9}, {%0,%1,%2,%3};"
        : "+f"(c[0]), "+f"(c[1]), "+f"(c[2]), "+f"(c[3])
        : "r"(a[0]), "r"(a[1]), "r"(a[2]), "r"(a[3]), "r"(b[0]), "r"(b[1]));
}

#define MT 96
#define AP 20
#define BP 136
#define SMEM_GEMM ((3 * MT * AP + 3 * 16 * BP) * 4)   // 49152

__global__ __launch_bounds__(256, 3) void mma_dual_gemm(
    const float* __restrict__ A1, const float* __restrict__ A2raw,
    const float* __restrict__ W1, const float* __restrict__ W2,
    const float* __restrict__ bias, float* __restrict__ C, int N, int doStats) {
    extern __shared__ float sm[];
    float* As = sm;                  // [3][96][AP]
    float* Bs = sm + 3 * MT * AP;    // [3][16][BP]

    int tid = threadIdx.x;
    int lane = tid & 31, wid = tid >> 5;
    int g = lane >> 2, tig = lane & 3;
    int wm = (wid & 1) * 48, wn = (wid >> 1) * 32;
    int m0 = blockIdx.x * MT, n0 = blockIdx.y * 128;

    int ar = tid >> 2, ac4 = (tid & 3) * 4;   // A: idx=tid (rows 0-63), idx=tid+256 (rows 64-95, tid<128)
    int bkr = tid >> 5, bnc = (tid & 31) * 4;

    float acc[3][4][4] = {};
    float4 sa[2];

    auto issue = [&](int chunk) {
        int ph = chunk >> 4;
        int k0 = (chunk & 15) * 16;
        int buf = chunk % 3;
        const float* W = ph ? W2 : W1;
        float* bb = Bs + (size_t)buf * 16 * BP;
        CP_ASYNC16((uint32_t)__cvta_generic_to_shared(bb + bkr * BP + bnc),
                   W + (size_t)(k0 + bkr) * N + n0 + bnc);
        CP_ASYNC16((uint32_t)__cvta_generic_to_shared(bb + (bkr + 8) * BP + bnc),
                   W + (size_t)(k0 + bkr + 8) * N + n0 + bnc);
        if (!ph) {
            float* ab = As + (size_t)buf * MT * AP;
#pragma unroll
            for (int q = 0; q < 2; q++) {
                if (q == 1 && tid >= 128) break;
                int r = ar + q * 64;
                int m = m0 + r;
                float* dst = ab + r * AP + ac4;
                if (m < N_NODES)
                    CP_ASYNC16((uint32_t)__cvta_generic_to_shared(dst),
                               A1 + (size_t)m * HID + k0 + ac4);
                else
                    *(float4*)dst = make_float4(0.f, 0.f, 0.f, 0.f);
            }
        } else {
#pragma unroll
            for (int q = 0; q < 2; q++) {
                if (q == 1 && tid >= 128) break;
                int r = ar + q * 64;
                int m = m0 + r;
                float4 v = (m < N_NODES)
                               ? *(const float4*)(A2raw + (size_t)m * HID + k0 + ac4)
                               : make_float4(0.f, 0.f, 0.f, 0.f);
                float4 scv = *(const float4*)(g_scale + k0 + ac4);
                float4 shv = *(const float4*)(g_shift + k0 + ac4);
                v.x = fmaxf(v.x * scv.x + shv.x, 0.f);
                v.y = fmaxf(v.y * scv.y + shv.y, 0.f);
                v.z = fmaxf(v.z * scv.z + shv.z, 0.f);
                v.w = fmaxf(v.w * scv.w + shv.w, 0.f);
                sa[q] = v;
            }
        }
        CP_COMMIT();
    };

    issue(0);

#pragma unroll 1
    for (int i = 0; i < 32; i++) {
        int buf = i % 3;
        if (i >= 16) {
            float* ab = As + (size_t)buf * MT * AP;
#pragma unroll
            for (int q = 0; q < 2; q++) {
                if (q == 1 && tid >= 128) break;
                int r = ar + q * 64;
                float4 v;
                v.x = to_tf32(sa[q].x); v.y = to_tf32(sa[q].y);
                v.z = to_tf32(sa[q].z); v.w = to_tf32(sa[q].w);
                *(float4*)(ab + r * AP + ac4) = v;
            }
        }
        if (i + 1 < 32) {
            issue(i + 1);
            CP_WAIT(1);
        } else {
            CP_WAIT(0);
        }
        __syncthreads();
        const float* ab = As + (size_t)buf * MT * AP;
        const float* bb = Bs + (size_t)buf * 16 * BP;
#pragma unroll
        for (int ks = 0; ks < 2; ks++) {
            int kb = ks * 8;
            uint32_t bf[4][2];
#pragma unroll
            for (int ni = 0; ni < 4; ni++) {
                int n = wn + ni * 8 + g;
                bf[ni][0] = __float_as_uint(bb[(kb + tig) * BP + n]);
                bf[ni][1] = __float_as_uint(bb[(kb + tig + 4) * BP + n]);
            }
#pragma unroll
            for (int mi = 0; mi < 3; mi++) {
                int m = wm + mi * 16 + g;
                uint32_t af[4];
                af[0] = __float_as_uint(ab[m * AP + kb + tig]);
                af[1] = __float_as_uint(ab[(m + 8) * AP + kb + tig]);
                af[2] = __float_as_uint(ab[m * AP + kb + tig + 4]);
                af[3] = __float_as_uint(ab[(m + 8) * AP + kb + tig + 4]);
#pragma unroll
                for (int ni = 0; ni < 4; ni++)
                    mma8(acc[mi][ni], af, bf[ni]);
            }
        }
    }

    // ---- epilogue: add bias, store, fused column stats ----
#pragma unroll
    for (int ni = 0; ni < 4; ni++) {
        int col = n0 + wn + ni * 8 + tig * 2;
        float b0 = bias[col], b1 = bias[col + 1];
        float s0 = 0.f, s1 = 0.f, q0 = 0.f, q1 = 0.f;
#pragma unroll
        for (int mi = 0; mi < 3; mi++) {
            int row0 = m0 + wm + mi * 16 + g;
            int row1 = row0 + 8;
            float v00 = acc[mi][ni][0] + b0, v01 = acc[mi][ni][1] + b1;
            float v10 = acc[mi][ni][2] + b0, v11 = acc[mi][ni][3] + b1;
            if (row0 < N_NODES) {
                *(float2*)(C + (size_t)row0 * N + col) = make_float2(v00, v01);
                s0 += v00; q0 += v00 * v00; s1 += v01; q1 += v01 * v01;
            }
            if (row1 < N_NODES) {
                *(float2*)(C + (size_t)row1 * N + col) = make_float2(v10, v11);
                s0 += v10; q0 += v10 * v10; s1 += v11; q1 += v11 * v11;
            }
        }
        if (doStats) {
#pragma unroll
            for (int off = 4; off < 32; off <<= 1) {
                s0 += __shfl_xor_sync(0xffffffffu, s0, off);
                s1 += __shfl_xor_sync(0xffffffffu, s1, off);
                q0 += __shfl_xor_sync(0xffffffffu, q0, off);
                q1 += __shfl_xor_sync(0xffffffffu, q1, off);
            }
            if (lane < 4) {
                atomicAdd(&g_stats[col], s0);
                atomicAdd(&g_stats[col + 1], s1);
                atomicAdd(&g_stats[HID + col], q0);
                atomicAdd(&g_stats[HID + col + 1], q1);
            }
        }
    }
}

// ---------------- orchestration ----------------------------------------------
extern "C" void kernel_launch(void* const* d_in, const int* in_sizes, int n_in,
                              void* d_out, int out_size) {
    const float* x    = (const float*)d_in[0];
    const int*   ei   = (const int*)d_in[1];
    const float* w_in = (const float*)d_in[2];
    const float* b_in = (const float*)d_in[3];
    const float* gi   = (const float*)d_in[4];
    const float* bei  = (const float*)d_in[5];
    const float* wl1  = (const float*)d_in[6];
    const float* bl1  = (const float*)d_in[7];
    const float* wr1  = (const float*)d_in[8];
    const float* g1   = (const float*)d_in[9];
    const float* be1  = (const float*)d_in[10];
    const float* wl2  = (const float*)d_in[11];
    const float* bl2  = (const float*)d_in[12];
    const float* wr2  = (const float*)d_in[13];
    const float* g2   = (const float*)d_in[14];
    const float* be2  = (const float*)d_in[15];
    const float* wl3  = (const float*)d_in[16];
    const float* bl3  = (const float*)d_in[17];
    const float* wr3  = (const float*)d_in[18];
    float* out = (float*)d_out;

    float *bufA, *bufB, *bufC, *rcnt, *wtf;
    int *deg, *rowstart, *cursor, *csrsrc, *bsum;
    cudaGetSymbolAddress((void**)&bufA, g_bufA);
    cudaGetSymbolAddress((void**)&bufB, g_bufB);
    cudaGetSymbolAddress((void**)&bufC, g_bufC);
    cudaGetSymbolAddress((void**)&rcnt, g_rcnt);
    cudaGetSymbolAddress((void**)&deg, g_deg);
    cudaGetSymbolAddress((void**)&rowstart, g_rowstart);
    cudaGetSymbolAddress((void**)&cursor, g_cursor);
    cudaGetSymbolAddress((void**)&csrsrc, g_csrsrc);
    cudaGetSymbolAddress((void**)&bsum, g_bsum);
    cudaGetSymbolAddress((void**)&wtf, g_wtf);

    const float* wl1t = wtf;
    const float* wr1t = wtf + 65536;
    const float* wl2t = wtf + 131072;
    const float* wr2t = wtf + 196608;
    const float* wl3t = wtf + 262144;
    const float* wr3t = wtf + 294912;

    cudaFuncSetAttribute(mma_dual_gemm,
                         cudaFuncAttributeMaxDynamicSharedMemorySize, SMEM_GEMM);

    // ---- CSR build + stats zero + weight pre-round ----
    zero_init<<<(N_NODES + 255) / 256, 256>>>(deg, rowstart);
    round_weights<<<327680 / 256, 256>>>(wl1, wr1, wl2, wr2, wl3, wr3);
    count_deg<<<(N_EDGES + 255) / 256, 256>>>(ei, deg);
    block_sums<<<SCAN_BLOCKS, 256>>>(deg, bsum);
    scan_emit<<<SCAN_BLOCKS, 256>>>(deg, bsum, rowstart, cursor, rcnt);
    fill_csr<<<(N_EDGES + 255) / 256, 256>>>(ei, cursor, csrsrc);

    // ---- input projection (fused stats) -> bufC raw; bn0 params ----
    input_proj<<<(N_NODES + 63) / 64, 256>>>(x, w_in, b_in, bufC);
    bn_finalize<<<1, HID>>>(gi, bei);

    const int MB = (N_NODES + MT - 1) / MT;  // 521
    dim3 ggrid(MB, HID / 128);               // 521 x 2
    dim3 ogrid(MB, EMB / 128);               // 521 x 1
    const int AGG_BLOCKS = N_NODES / 4;      // 12500

    // ---- SAGE layer 1: raw=bufC (bn0 lazily) -> bufA raw; bn1 ----
    agg_gather_bn<<<AGG_BLOCKS, 256>>>(rowstart, csrsrc, rcnt, bufC, bufB);
    mma_dual_gemm<<<ggrid, 256, SMEM_GEMM>>>(bufB, bufC, wl1t, wr1t, bl1, bufA, HID, 1);
    bn_finalize<<<1, HID>>>(g1, be1);

    // ---- SAGE layer 2: raw=bufA -> bufC raw; bn2 ----
    agg_gather_bn<<<AGG_BLOCKS, 256>>>(rowstart, csrsrc, rcnt, bufA, bufB);
    mma_dual_gemm<<<ggrid, 256, SMEM_GEMM>>>(bufB, bufA, wl2t, wr2t, bl2, bufC, HID, 1);
    bn_finalize<<<1, HID>>>(g2, be2);

    // ---- SAGE layer 3: raw=bufC -> out (no BN) ----
    agg_gather_bn<<<AGG_BLOCKS, 256>>>(rowstart, csrsrc, rcnt, bufC, bufB);
    mma_dual_gemm<<<ogrid, 256, SMEM_GEMM>>>(bufB, bufC, wl3t, wr3t, bl3, out, EMB, 0);
}

// round 16
// speedup vs baseline: 1.0649x; 1.0649x over previous
#include <cuda_runtime.h>
#include <cstdint>

#define N_NODES 50000
#define N_EDGES 800000
#define HID     256
#define EMB     128
#define IN_F    10
#define BN_EPS  1e-5f
#define SCAN_BLOCKS ((N_NODES + 1023) / 1024)   // 49

// ---------------- scratch (static device globals; no allocation) ------------
__device__ float g_bufA[N_NODES * HID];
__device__ float g_bufB[N_NODES * HID];   // agg (gather target, tf32-rounded)
__device__ float g_bufC[N_NODES * HID];
__device__ float g_rcnt[N_NODES];
__device__ int   g_deg[N_NODES];
__device__ int   g_rowstart[N_NODES + 1];
__device__ int   g_cursor[N_NODES];
__device__ int   g_csrsrc[N_EDGES];
__device__ int   g_bsum[SCAN_BLOCKS];
__device__ float g_stats[2 * HID];
__device__ float g_scale[HID];
__device__ float g_shift[HID];
__device__ float g_wtf[4 * 65536 + 2 * 32768];  // tf32-rounded weights

__device__ __forceinline__ float to_tf32(float x) {
    float y;
    asm("cvt.rna.tf32.f32 %0, %1;" : "=f"(y) : "f"(x));
    return y;
}

#define CP_ASYNC16(dst_u32, src_ptr) \
    asm volatile("cp.async.ca.shared.global [%0], [%1], 16;" \
                 :: "r"(dst_u32), "l"(src_ptr) : "memory")
#define CP_COMMIT() asm volatile("cp.async.commit_group;" ::: "memory")
#define CP_WAIT(n)  asm volatile("cp.async.wait_group %0;" :: "n"(n) : "memory")

// ---------------- CSR construction -----------------------------------------
__global__ void zero_init(int* __restrict__ deg, int* __restrict__ rowstart) {
    int i = blockIdx.x * blockDim.x + threadIdx.x;
    if (i < N_NODES) deg[i] = 0;
    if (i < 2 * HID) g_stats[i] = 0.f;
    if (i == 0) rowstart[N_NODES] = N_EDGES;
}

__global__ void count_deg(const int* __restrict__ ei, int* __restrict__ deg) {
    int e = blockIdx.x * blockDim.x + threadIdx.x;
    if (e < N_EDGES) atomicAdd(deg + ei[N_EDGES + e], 1);
}

__global__ __launch_bounds__(256) void block_sums(const int* __restrict__ deg,
                                                  int* __restrict__ bsum) {
    __shared__ int ws[8];
    int t = threadIdx.x;
    int base = blockIdx.x * 1024 + t * 4;
    int s = 0;
#pragma unroll
    for (int k = 0; k < 4; k++) {
        int idx = base + k;
        if (idx < N_NODES) s += deg[idx];
    }
#pragma unroll
    for (int off = 16; off; off >>= 1) s += __shfl_down_sync(0xffffffffu, s, off);
    if ((t & 31) == 0) ws[t >> 5] = s;
    __syncthreads();
    if (t < 8) {
        int v = ws[t];
#pragma unroll
        for (int off = 4; off; off >>= 1) v += __shfl_down_sync(0xffu, v, off);
        if (t == 0) bsum[blockIdx.x] = v;
    }
}

__global__ __launch_bounds__(256) void scan_emit(const int* __restrict__ deg,
                                                 const int* __restrict__ bsum,
                                                 int* __restrict__ rowstart,
                                                 int* __restrict__ cursor,
                                                 float* __restrict__ rcnt) {
    __shared__ int s_part[2];
    __shared__ int warpsum[8];
    int t = threadIdx.x;
    int b = blockIdx.x;
    int lane = t & 31, wid = t >> 5;

    if (t < 64) {
        int v = (t < b) ? bsum[t] : 0;
#pragma unroll
        for (int off = 16; off; off >>= 1) v += __shfl_down_sync(0xffffffffu, v, off);
        if (lane == 0) s_part[wid] = v;
    }

    int base = b * 1024 + t * 4;
    int d[4];
    int tsum = 0;
#pragma unroll
    for (int k = 0; k < 4; k++) {
        int idx = base + k;
        d[k] = (idx < N_NODES) ? deg[idx] : 0;
        tsum += d[k];
    }
    int incl = tsum;
#pragma unroll
    for (int off = 1; off < 32; off <<= 1) {
        int v = __shfl_up_sync(0xffffffffu, incl, off);
        if (lane >= off) incl += v;
    }
    if (lane == 31) warpsum[wid] = incl;
    __syncthreads();
    if (t < 8) {
        int v = warpsum[t];
#pragma unroll
        for (int off = 1; off < 8; off <<= 1) {
            int u = __shfl_up_sync(0xffu, v, off);
            if (t >= off) v += u;
        }
        warpsum[t] = v;
    }
    __syncthreads();

    int run = (s_part[0] + s_part[1]) + (incl - tsum) + (wid ? warpsum[wid - 1] : 0);
#pragma unroll
    for (int k = 0; k < 4; k++) {
        int idx = base + k;
        if (idx < N_NODES) {
            rowstart[idx] = run;
            cursor[idx] = run;
            rcnt[idx] = 1.0f / fmaxf((float)d[k], 1.0f);
            run += d[k];
        }
    }
}

__global__ void fill_csr(const int* __restrict__ ei, int* __restrict__ cursor,
                         int* __restrict__ csrsrc) {
    int e = blockIdx.x * blockDim.x + threadIdx.x;
    if (e < N_EDGES) {
        int dst = ei[N_EDGES + e];
        int p = atomicAdd(cursor + dst, 1);
        csrsrc[p] = ei[e];
    }
}

// ---------------- weight pre-rounding (fp32 -> tf32 values) ------------------
__global__ void round_weights(const float* __restrict__ w1, const float* __restrict__ w2,
                              const float* __restrict__ w3, const float* __restrict__ w4,
                              const float* __restrict__ w5, const float* __restrict__ w6) {
    int i = blockIdx.x * blockDim.x + threadIdx.x;  // < 327680
    float v;
    if (i < 262144) {
        int seg = i >> 16, off = i & 65535;
        const float* s = (seg == 0) ? w1 : (seg == 1) ? w2 : (seg == 2) ? w3 : w4;
        v = s[off];
    } else {
        int j = i - 262144;
        v = (j < 32768) ? w5[j] : w6[j - 32768];
    }
    g_wtf[i] = to_tf32(v);
}

// ---------------- input projection (+ fused column stats), 64 rows/block ----
__global__ __launch_bounds__(256) void input_proj(const float* __restrict__ x,
                                                  const float* __restrict__ w,
                                                  const float* __restrict__ b,
                                                  float* __restrict__ out) {
    __shared__ float ws[IN_F * HID];
    __shared__ float xs[64 * IN_F];
    int t = threadIdx.x;
    for (int i = t; i < IN_F * HID; i += 256) ws[i] = w[i];
    int r0 = blockIdx.x * 64;
    int nr = min(64, N_NODES - r0);
    for (int i = t; i < nr * IN_F; i += 256) xs[i] = x[(size_t)r0 * IN_F + i];
    __syncthreads();
    float bb = b[t];
    float s = 0.f, s2 = 0.f;
    for (int r = 0; r < nr; r++) {
        float v = bb;
#pragma unroll
        for (int k = 0; k < IN_F; k++) v += xs[r * IN_F + k] * ws[k * HID + t];
        out[(size_t)(r0 + r) * HID + t] = v;
        s += v; s2 += v * v;
    }
    atomicAdd(&g_stats[t], s);
    atomicAdd(&g_stats[HID + t], s2);
}

// ---------------- BatchNorm params (also re-zeroes stats) --------------------
__global__ void bn_finalize(const float* __restrict__ g, const float* __restrict__ be) {
    int c = threadIdx.x;
    float mu  = g_stats[c] * (1.0f / N_NODES);
    float var = g_stats[HID + c] * (1.0f / N_NODES) - mu * mu;
    float sc  = g[c] * rsqrtf(var + BN_EPS);
    g_scale[c] = sc;
    g_shift[c] = be[c] - mu * sc;
    g_stats[c] = 0.f;
    g_stats[HID + c] = 0.f;
}

// ---------------- aggregation: gather-mean of relu(bn(raw)), tf32 output -----
// 4 nodes/block, 64 threads/node, float4/thread, 8-neighbor unroll (MLP=8).
__global__ __launch_bounds__(256) void agg_gather_bn(const int* __restrict__ rowstart,
                                                     const int* __restrict__ csrsrc,
                                                     const float* __restrict__ rcnt,
                                                     const float* __restrict__ raw,
                                                     float* __restrict__ agg) {
    int node = blockIdx.x * 4 + (threadIdx.x >> 6);
    int c = (threadIdx.x & 63) * 4;
    float4 sc = *(const float4*)(g_scale + c);
    float4 sh = *(const float4*)(g_shift + c);
    int j = rowstart[node];
    int e = rowstart[node + 1];
    float4 acc = make_float4(0.f, 0.f, 0.f, 0.f);
    for (; j + 8 <= e; j += 8) {
        int sx[8];
#pragma unroll
        for (int k = 0; k < 8; k++) sx[k] = __ldg(csrsrc + j + k);
        float4 v[8];
#pragma unroll
        for (int k = 0; k < 8; k++) v[k] = *(const float4*)(raw + (size_t)sx[k] * HID + c);
#pragma unroll
        for (int k = 0; k < 8; k++) {
            acc.x += fmaxf(v[k].x * sc.x + sh.x, 0.f);
            acc.y += fmaxf(v[k].y * sc.y + sh.y, 0.f);
            acc.z += fmaxf(v[k].z * sc.z + sh.z, 0.f);
            acc.w += fmaxf(v[k].w * sc.w + sh.w, 0.f);
        }
    }
    for (; j < e; j++) {
        int s0 = __ldg(csrsrc + j);
        float4 v0 = *(const float4*)(raw + (size_t)s0 * HID + c);
        acc.x += fmaxf(v0.x * sc.x + sh.x, 0.f);
        acc.y += fmaxf(v0.y * sc.y + sh.y, 0.f);
        acc.z += fmaxf(v0.z * sc.z + sh.z, 0.f);
        acc.w += fmaxf(v0.w * sc.w + sh.w, 0.f);
    }
    float r = rcnt[node];
    float4 o;
    o.x = to_tf32(acc.x * r); o.y = to_tf32(acc.y * r);
    o.z = to_tf32(acc.z * r); o.w = to_tf32(acc.w * r);
    *(float4*)(agg + (size_t)node * HID + c) = o;
}

// ---------------- TF32 mma.sync dual GEMM (R13: 128-M tile, occ 2) -----------
__device__ __forceinline__ void mma8(float* c, const uint32_t* a, const uint32_t* b) {
    asm volatile(
        "mma.sync.aligned.m16n8k8.row.col.f32.tf32.tf32.f32 "
        "{%0,%1,%2,%3}, {%4,%5,%6,%7}, {%8,%9}, {%0,%1,%2,%3};"
        : "+f"(c[0]), "+f"(c[1]), "+f"(c[2]), "+f"(c[3])
        : "r"(a[0]), "r"(a[1]), "r"(a[2]), "r"(a[3]), "r"(b[0]), "r"(b[1]));
}

#define AP 20
#define BP 136
#define SMEM_GEMM ((3 * 128 * AP + 3 * 16 * BP) * 4)

__global__ __launch_bounds__(256, 2) void mma_dual_gemm(
    const float* __restrict__ A1, const float* __restrict__ A2raw,
    const float* __restrict__ W1, const float* __restrict__ W2,
    const float* __restrict__ bias, float* __restrict__ C, int N, int doStats) {
    extern __shared__ float sm[];
    float* As = sm;                  // [3][128][AP]
    float* Bs = sm + 3 * 128 * AP;   // [3][16][BP]

    int tid = threadIdx.x;
    int lane = tid & 31, wid = tid >> 5;
    int g = lane >> 2, tig = lane & 3;
    int wm = (wid & 1) * 64, wn = (wid >> 1) * 32;
    int m0 = blockIdx.x * 128, n0 = blockIdx.y * 128;

    int ar = tid >> 2, ac4 = (tid & 3) * 4;
    int bkr = tid >> 5, bnc = (tid & 31) * 4;

    float acc[4][4][4] = {};
    float4 sa[2];

    auto issue = [&](int chunk) {
        int ph = chunk >> 4;
        int k0 = (chunk & 15) * 16;
        int buf = chunk % 3;
        const float* W = ph ? W2 : W1;
        float* bb = Bs + (size_t)buf * 16 * BP;
        CP_ASYNC16((uint32_t)__cvta_generic_to_shared(bb + bkr * BP + bnc),
                   W + (size_t)(k0 + bkr) * N + n0 + bnc);
        CP_ASYNC16((uint32_t)__cvta_generic_to_shared(bb + (bkr + 8) * BP + bnc),
                   W + (size_t)(k0 + bkr + 8) * N + n0 + bnc);
        if (!ph) {
            float* ab = As + (size_t)buf * 128 * AP;
#pragma unroll
            for (int q = 0; q < 2; q++) {
                int r = ar + q * 64;
                int m = m0 + r;
                float* dst = ab + r * AP + ac4;
                if (m < N_NODES)
                    CP_ASYNC16((uint32_t)__cvta_generic_to_shared(dst),
                               A1 + (size_t)m * HID + k0 + ac4);
                else
                    *(float4*)dst = make_float4(0.f, 0.f, 0.f, 0.f);
            }
        } else {
#pragma unroll
            for (int q = 0; q < 2; q++) {
                int r = ar + q * 64;
                int m = m0 + r;
                float4 v = (m < N_NODES)
                               ? *(const float4*)(A2raw + (size_t)m * HID + k0 + ac4)
                               : make_float4(0.f, 0.f, 0.f, 0.f);
                float4 scv = *(const float4*)(g_scale + k0 + ac4);
                float4 shv = *(const float4*)(g_shift + k0 + ac4);
                v.x = fmaxf(v.x * scv.x + shv.x, 0.f);
                v.y = fmaxf(v.y * scv.y + shv.y, 0.f);
                v.z = fmaxf(v.z * scv.z + shv.z, 0.f);
                v.w = fmaxf(v.w * scv.w + shv.w, 0.f);
                sa[q] = v;
            }
        }
        CP_COMMIT();
    };

    issue(0);

#pragma unroll 1
    for (int i = 0; i < 32; i++) {
        int buf = i % 3;
        if (i >= 16) {
            float* ab = As + (size_t)buf * 128 * AP;
#pragma unroll
            for (int q = 0; q < 2; q++) {
                int r = ar + q * 64;
                float4 v;
                v.x = to_tf32(sa[q].x); v.y = to_tf32(sa[q].y);
                v.z = to_tf32(sa[q].z); v.w = to_tf32(sa[q].w);
                *(float4*)(ab + r * AP + ac4) = v;
            }
        }
        if (i + 1 < 32) {
            issue(i + 1);
            CP_WAIT(1);
        } else {
            CP_WAIT(0);
        }
        __syncthreads();
        const float* ab = As + (size_t)buf * 128 * AP;
        const float* bb = Bs + (size_t)buf * 16 * BP;
#pragma unroll
        for (int ks = 0; ks < 2; ks++) {
            int kb = ks * 8;
            uint32_t af[4][4];
#pragma unroll
            for (int mi = 0; mi < 4; mi++) {
                int m = wm + mi * 16 + g;
                af[mi][0] = __float_as_uint(ab[m * AP + kb + tig]);
                af[mi][1] = __float_as_uint(ab[(m + 8) * AP + kb + tig]);
                af[mi][2] = __float_as_uint(ab[m * AP + kb + tig + 4]);
                af[mi][3] = __float_as_uint(ab[(m + 8) * AP + kb + tig + 4]);
            }
            uint32_t bf[4][2];
#pragma unroll
            for (int ni = 0; ni < 4; ni++) {
                int n = wn + ni * 8 + g;
                bf[ni][0] = __float_as_uint(bb[(kb + tig) * BP + n]);
                bf[ni][1] = __float_as_uint(bb[(kb + tig + 4) * BP + n]);
            }
#pragma unroll
            for (int mi = 0; mi < 4; mi++)
#pragma unroll
                for (int ni = 0; ni < 4; ni++)
                    mma8(acc[mi][ni], af[mi], bf[ni]);
        }
    }

    // ---- epilogue: add bias, store, fused column stats ----
#pragma unroll
    for (int ni = 0; ni < 4; ni++) {
        int col = n0 + wn + ni * 8 + tig * 2;
        float b0 = bias[col], b1 = bias[col + 1];
        float s0 = 0.f, s1 = 0.f, q0 = 0.f, q1 = 0.f;
#pragma unroll
        for (int mi = 0; mi < 4; mi++) {
            int row0 = m0 + wm + mi * 16 + g;
            int row1 = row0 + 8;
            float v00 = acc[mi][ni][0] + b0, v01 = acc[mi][ni][1] + b1;
            float v10 = acc[mi][ni][2] + b0, v11 = acc[mi][ni][3] + b1;
            if (row0 < N_NODES) {
                *(float2*)(C + (size_t)row0 * N + col) = make_float2(v00, v01);
                s0 += v00; q0 += v00 * v00; s1 += v01; q1 += v01 * v01;
            }
            if (row1 < N_NODES) {
                *(float2*)(C + (size_t)row1 * N + col) = make_float2(v10, v11);
                s0 += v10; q0 += v10 * v10; s1 += v11; q1 += v11 * v11;
            }
        }
        if (doStats) {
#pragma unroll
            for (int off = 4; off < 32; off <<= 1) {
                s0 += __shfl_xor_sync(0xffffffffu, s0, off);
                s1 += __shfl_xor_sync(0xffffffffu, s1, off);
                q0 += __shfl_xor_sync(0xffffffffu, q0, off);
                q1 += __shfl_xor_sync(0xffffffffu, q1, off);
            }
            if (lane < 4) {
                atomicAdd(&g_stats[col], s0);
                atomicAdd(&g_stats[col + 1], s1);
                atomicAdd(&g_stats[HID + col], q0);
                atomicAdd(&g_stats[HID + col + 1], q1);
            }
        }
    }
}

// ---------------- orchestration ----------------------------------------------
extern "C" void kernel_launch(void* const* d_in, const int* in_sizes, int n_in,
                              void* d_out, int out_size) {
    const float* x    = (const float*)d_in[0];
    const int*   ei   = (const int*)d_in[1];
    const float* w_in = (const float*)d_in[2];
    const float* b_in = (const float*)d_in[3];
    const float* gi   = (const float*)d_in[4];
    const float* bei  = (const float*)d_in[5];
    const float* wl1  = (const float*)d_in[6];
    const float* bl1  = (const float*)d_in[7];
    const float* wr1  = (const float*)d_in[8];
    const float* g1   = (const float*)d_in[9];
    const float* be1  = (const float*)d_in[10];
    const float* wl2  = (const float*)d_in[11];
    const float* bl2  = (const float*)d_in[12];
    const float* wr2  = (const float*)d_in[13];
    const float* g2   = (const float*)d_in[14];
    const float* be2  = (const float*)d_in[15];
    const float* wl3  = (const float*)d_in[16];
    const float* bl3  = (const float*)d_in[17];
    const float* wr3  = (const float*)d_in[18];
    float* out = (float*)d_out;

    float *bufA, *bufB, *bufC, *rcnt, *wtf;
    int *deg, *rowstart, *cursor, *csrsrc, *bsum;
    cudaGetSymbolAddress((void**)&bufA, g_bufA);
    cudaGetSymbolAddress((void**)&bufB, g_bufB);
    cudaGetSymbolAddress((void**)&bufC, g_bufC);
    cudaGetSymbolAddress((void**)&rcnt, g_rcnt);
    cudaGetSymbolAddress((void**)&deg, g_deg);
    cudaGetSymbolAddress((void**)&rowstart, g_rowstart);
    cudaGetSymbolAddress((void**)&cursor, g_cursor);
    cudaGetSymbolAddress((void**)&csrsrc, g_csrsrc);
    cudaGetSymbolAddress((void**)&bsum, g_bsum);
    cudaGetSymbolAddress((void**)&wtf, g_wtf);

    const float* wl1t = wtf;
    const float* wr1t = wtf + 65536;
    const float* wl2t = wtf + 131072;
    const float* wr2t = wtf + 196608;
    const float* wl3t = wtf + 262144;
    const float* wr3t = wtf + 294912;

    cudaFuncSetAttribute(mma_dual_gemm,
                         cudaFuncAttributeMaxDynamicSharedMemorySize, SMEM_GEMM);

    // ---- CSR build + stats zero + weight pre-round ----
    zero_init<<<(N_NODES + 255) / 256, 256>>>(deg, rowstart);
    round_weights<<<327680 / 256, 256>>>(wl1, wr1, wl2, wr2, wl3, wr3);
    count_deg<<<(N_EDGES + 255) / 256, 256>>>(ei, deg);
    block_sums<<<SCAN_BLOCKS, 256>>>(deg, bsum);
    scan_emit<<<SCAN_BLOCKS, 256>>>(deg, bsum, rowstart, cursor, rcnt);
    fill_csr<<<(N_EDGES + 255) / 256, 256>>>(ei, cursor, csrsrc);

    // ---- input projection (fused stats) -> bufC raw; bn0 params ----
    input_proj<<<(N_NODES + 63) / 64, 256>>>(x, w_in, b_in, bufC);
    bn_finalize<<<1, HID>>>(gi, bei);

    const int MB = (N_NODES + 127) / 128;  // 391
    dim3 ggrid(MB, HID / 128);             // 391 x 2
    dim3 ogrid(MB, EMB / 128);             // 391 x 1
    const int AGG_BLOCKS = N_NODES / 4;    // 12500

    // ---- SAGE layer 1: raw=bufC (bn0 lazily) -> bufA raw; bn1 ----
    agg_gather_bn<<<AGG_BLOCKS, 256>>>(rowstart, csrsrc, rcnt, bufC, bufB);
    mma_dual_gemm<<<ggrid, 256, SMEM_GEMM>>>(bufB, bufC, wl1t, wr1t, bl1, bufA, HID, 1);
    bn_finalize<<<1, HID>>>(g1, be1);

    // ---- SAGE layer 2: raw=bufA -> bufC raw; bn2 ----
    agg_gather_bn<<<AGG_BLOCKS, 256>>>(rowstart, csrsrc, rcnt, bufA, bufB);
    mma_dual_gemm<<<ggrid, 256, SMEM_GEMM>>>(bufB, bufA, wl2t, wr2t, bl2, bufC, HID, 1);
    bn_finalize<<<1, HID>>>(g2, be2);

    // ---- SAGE layer 3: raw=bufC -> out (no BN) ----
    agg_gather_bn<<<AGG_BLOCKS, 256>>>(rowstart, csrsrc, rcnt, bufC, bufB);
    mma_dual_gemm<<<ogrid, 256, SMEM_GEMM>>>(bufB, bufC, wl3t, wr3t, bl3, out, EMB, 0);
}

// round 17
// speedup vs baseline: 1.1342x; 1.0651x over previous
#include <cuda_runtime.h>
#include <cstdint>

#define N_NODES 50000
#define N_EDGES 800000
#define HID     256
#define EMB     128
#define IN_F    10
#define BN_EPS  1e-5f
#define SCAN_BLOCKS ((N_NODES + 1023) / 1024)   // 49

// ---------------- scratch (static device globals; no allocation) ------------
__device__ float g_bufA[N_NODES * HID];
__device__ float g_bufB[N_NODES * HID];   // agg (gather target, tf32-rounded)
__device__ float g_bufC[N_NODES * HID];
__device__ float g_rcnt[N_NODES];
__device__ int   g_deg[N_NODES];
__device__ int   g_rowstart[N_NODES + 1];
__device__ int   g_cursor[N_NODES];
__device__ int   g_csrsrc[N_EDGES];
__device__ int   g_bsum[SCAN_BLOCKS];
__device__ float g_stats[2 * HID];
__device__ float g_scale[HID];
__device__ float g_shift[HID];
__device__ float g_wtf[4 * 65536 + 2 * 32768];  // tf32-rounded weights

__device__ __forceinline__ float to_tf32(float x) {
    float y;
    asm("cvt.rna.tf32.f32 %0, %1;" : "=f"(y) : "f"(x));
    return y;
}

#define CP_ASYNC16(dst_u32, src_ptr) \
    asm volatile("cp.async.ca.shared.global [%0], [%1], 16;" \
                 :: "r"(dst_u32), "l"(src_ptr) : "memory")
#define CP_COMMIT() asm volatile("cp.async.commit_group;" ::: "memory")
#define CP_WAIT(n)  asm volatile("cp.async.wait_group %0;" :: "n"(n) : "memory")

// ---------------- CSR construction -----------------------------------------
__global__ void zero_init(int* __restrict__ deg, int* __restrict__ rowstart) {
    int i = blockIdx.x * blockDim.x + threadIdx.x;
    if (i < N_NODES) deg[i] = 0;
    if (i < 2 * HID) g_stats[i] = 0.f;
    if (i == 0) rowstart[N_NODES] = N_EDGES;
}

__global__ void count_deg(const int* __restrict__ ei, int* __restrict__ deg) {
    int e = blockIdx.x * blockDim.x + threadIdx.x;
    if (e < N_EDGES) atomicAdd(deg + ei[N_EDGES + e], 1);
}

__global__ __launch_bounds__(256) void block_sums(const int* __restrict__ deg,
                                                  int* __restrict__ bsum) {
    __shared__ int ws[8];
    int t = threadIdx.x;
    int base = blockIdx.x * 1024 + t * 4;
    int s = 0;
#pragma unroll
    for (int k = 0; k < 4; k++) {
        int idx = base + k;
        if (idx < N_NODES) s += deg[idx];
    }
#pragma unroll
    for (int off = 16; off; off >>= 1) s += __shfl_down_sync(0xffffffffu, s, off);
    if ((t & 31) == 0) ws[t >> 5] = s;
    __syncthreads();
    if (t < 8) {
        int v = ws[t];
#pragma unroll
        for (int off = 4; off; off >>= 1) v += __shfl_down_sync(0xffu, v, off);
        if (t == 0) bsum[blockIdx.x] = v;
    }
}

__global__ __launch_bounds__(256) void scan_emit(const int* __restrict__ deg,
                                                 const int* __restrict__ bsum,
                                                 int* __restrict__ rowstart,
                                                 int* __restrict__ cursor,
                                                 float* __restrict__ rcnt) {
    __shared__ int s_part[2];
    __shared__ int warpsum[8];
    int t = threadIdx.x;
    int b = blockIdx.x;
    int lane = t & 31, wid = t >> 5;

    if (t < 64) {
        int v = (t < b) ? bsum[t] : 0;
#pragma unroll
        for (int off = 16; off; off >>= 1) v += __shfl_down_sync(0xffffffffu, v, off);
        if (lane == 0) s_part[wid] = v;
    }

    int base = b * 1024 + t * 4;
    int d[4];
    int tsum = 0;
#pragma unroll
    for (int k = 0; k < 4; k++) {
        int idx = base + k;
        d[k] = (idx < N_NODES) ? deg[idx] : 0;
        tsum += d[k];
    }
    int incl = tsum;
#pragma unroll
    for (int off = 1; off < 32; off <<= 1) {
        int v = __shfl_up_sync(0xffffffffu, incl, off);
        if (lane >= off) incl += v;
    }
    if (lane == 31) warpsum[wid] = incl;
    __syncthreads();
    if (t < 8) {
        int v = warpsum[t];
#pragma unroll
        for (int off = 1; off < 8; off <<= 1) {
            int u = __shfl_up_sync(0xffu, v, off);
            if (t >= off) v += u;
        }
        warpsum[t] = v;
    }
    __syncthreads();

    int run = (s_part[0] + s_part[1]) + (incl - tsum) + (wid ? warpsum[wid - 1] : 0);
#pragma unroll
    for (int k = 0; k < 4; k++) {
        int idx = base + k;
        if (idx < N_NODES) {
            rowstart[idx] = run;
            cursor[idx] = run;
            rcnt[idx] = 1.0f / fmaxf((float)d[k], 1.0f);
            run += d[k];
        }
    }
}

__global__ void fill_csr(const int* __restrict__ ei, int* __restrict__ cursor,
                         int* __restrict__ csrsrc) {
    int e = blockIdx.x * blockDim.x + threadIdx.x;
    if (e < N_EDGES) {
        int dst = ei[N_EDGES + e];
        int p = atomicAdd(cursor + dst, 1);
        csrsrc[p] = ei[e];
    }
}

// ---------------- weight pre-rounding (fp32 -> tf32 values) ------------------
__global__ void round_weights(const float* __restrict__ w1, const float* __restrict__ w2,
                              const float* __restrict__ w3, const float* __restrict__ w4,
                              const float* __restrict__ w5, const float* __restrict__ w6) {
    int i = blockIdx.x * blockDim.x + threadIdx.x;  // < 327680
    float v;
    if (i < 262144) {
        int seg = i >> 16, off = i & 65535;
        const float* s = (seg == 0) ? w1 : (seg == 1) ? w2 : (seg == 2) ? w3 : w4;
        v = s[off];
    } else {
        int j = i - 262144;
        v = (j < 32768) ? w5[j] : w6[j - 32768];
    }
    g_wtf[i] = to_tf32(v);
}

// ---------------- input projection (+ fused column stats), 64 rows/block ----
__global__ __launch_bounds__(256) void input_proj(const float* __restrict__ x,
                                                  const float* __restrict__ w,
                                                  const float* __restrict__ b,
                                                  float* __restrict__ out) {
    __shared__ float ws[IN_F * HID];
    __shared__ float xs[64 * IN_F];
    int t = threadIdx.x;
    for (int i = t; i < IN_F * HID; i += 256) ws[i] = w[i];
    int r0 = blockIdx.x * 64;
    int nr = min(64, N_NODES - r0);
    for (int i = t; i < nr * IN_F; i += 256) xs[i] = x[(size_t)r0 * IN_F + i];
    __syncthreads();
    float bb = b[t];
    float s = 0.f, s2 = 0.f;
    for (int r = 0; r < nr; r++) {
        float v = bb;
#pragma unroll
        for (int k = 0; k < IN_F; k++) v += xs[r * IN_F + k] * ws[k * HID + t];
        out[(size_t)(r0 + r) * HID + t] = v;
        s += v; s2 += v * v;
    }
    atomicAdd(&g_stats[t], s);
    atomicAdd(&g_stats[HID + t], s2);
}

// ---------------- BatchNorm params (also re-zeroes stats) --------------------
__global__ void bn_finalize(const float* __restrict__ g, const float* __restrict__ be) {
    int c = threadIdx.x;
    float mu  = g_stats[c] * (1.0f / N_NODES);
    float var = g_stats[HID + c] * (1.0f / N_NODES) - mu * mu;
    float sc  = g[c] * rsqrtf(var + BN_EPS);
    g_scale[c] = sc;
    g_shift[c] = be[c] - mu * sc;
    g_stats[c] = 0.f;
    g_stats[HID + c] = 0.f;
}

// ---------------- aggregation: gather-mean of relu(bn(raw)), tf32 output -----
// 4 nodes/block, 64 threads/node, float4/thread, 8-neighbor unroll (MLP=8).
__global__ __launch_bounds__(256) void agg_gather_bn(const int* __restrict__ rowstart,
                                                     const int* __restrict__ csrsrc,
                                                     const float* __restrict__ rcnt,
                                                     const float* __restrict__ raw,
                                                     float* __restrict__ agg) {
    int node = blockIdx.x * 4 + (threadIdx.x >> 6);
    int c = (threadIdx.x & 63) * 4;
    float4 sc = *(const float4*)(g_scale + c);
    float4 sh = *(const float4*)(g_shift + c);
    int j = rowstart[node];
    int e = rowstart[node + 1];
    float4 acc = make_float4(0.f, 0.f, 0.f, 0.f);
    for (; j + 8 <= e; j += 8) {
        int sx[8];
#pragma unroll
        for (int k = 0; k < 8; k++) sx[k] = __ldg(csrsrc + j + k);
        float4 v[8];
#pragma unroll
        for (int k = 0; k < 8; k++) v[k] = *(const float4*)(raw + (size_t)sx[k] * HID + c);
#pragma unroll
        for (int k = 0; k < 8; k++) {
            acc.x += fmaxf(v[k].x * sc.x + sh.x, 0.f);
            acc.y += fmaxf(v[k].y * sc.y + sh.y, 0.f);
            acc.z += fmaxf(v[k].z * sc.z + sh.z, 0.f);
            acc.w += fmaxf(v[k].w * sc.w + sh.w, 0.f);
        }
    }
    for (; j < e; j++) {
        int s0 = __ldg(csrsrc + j);
        float4 v0 = *(const float4*)(raw + (size_t)s0 * HID + c);
        acc.x += fmaxf(v0.x * sc.x + sh.x, 0.f);
        acc.y += fmaxf(v0.y * sc.y + sh.y, 0.f);
        acc.z += fmaxf(v0.z * sc.z + sh.z, 0.f);
        acc.w += fmaxf(v0.w * sc.w + sh.w, 0.f);
    }
    float r = rcnt[node];
    float4 o;
    o.x = to_tf32(acc.x * r); o.y = to_tf32(acc.y * r);
    o.z = to_tf32(acc.z * r); o.w = to_tf32(acc.w * r);
    *(float4*)(agg + (size_t)node * HID + c) = o;
}

// ---------------- TF32 mma.sync dual GEMM (128-M tile, occ 2, K-chunk 32) ----
__device__ __forceinline__ void mma8(float* c, const uint32_t* a, const uint32_t* b) {
    asm volatile(
        "mma.sync.aligned.m16n8k8.row.col.f32.tf32.tf32.f32 "
        "{%0,%1,%2,%3}, {%4,%5,%6,%7}, {%8,%9}, {%0,%1,%2,%3};"
        : "+f"(c[0]), "+f"(c[1]), "+f"(c[2]), "+f"(c[3])
        : "r"(a[0]), "r"(a[1]), "r"(a[2]), "r"(a[3]), "r"(b[0]), "r"(b[1]));
}

#define AP 36
#define BP 136
#define SMEM_GEMM ((3 * 128 * AP + 3 * 32 * BP) * 4)   // 107520

__global__ __launch_bounds__(256, 2) void mma_dual_gemm(
    const float* __restrict__ A1, const float* __restrict__ A2raw,
    const float* __restrict__ W1, const float* __restrict__ W2,
    const float* __restrict__ bias, float* __restrict__ C, int N, int doStats) {
    extern __shared__ float sm[];
    float* As = sm;                  // [3][128][AP]
    float* Bs = sm + 3 * 128 * AP;   // [3][32][BP]

    int tid = threadIdx.x;
    int lane = tid & 31, wid = tid >> 5;
    int g = lane >> 2, tig = lane & 3;
    int wm = (wid & 1) * 64, wn = (wid >> 1) * 32;
    int m0 = blockIdx.x * 128, n0 = blockIdx.y * 128;

    int ar = tid >> 3, ac4 = (tid & 7) * 4;   // A: 128 rows x 8 f4/row; q stride 32 rows
    int bkr = tid >> 5, bnc = (tid & 31) * 4; // B: rows bkr + 8j

    float acc[4][4][4] = {};
    float4 sa[4];

    auto issue = [&](int chunk) {
        int ph = chunk >> 3;
        int k0 = (chunk & 7) * 32;
        int buf = chunk % 3;
        const float* W = ph ? W2 : W1;
        float* bb = Bs + (size_t)buf * 32 * BP;
#pragma unroll
        for (int j = 0; j < 4; j++) {
            CP_ASYNC16((uint32_t)__cvta_generic_to_shared(bb + (bkr + 8 * j) * BP + bnc),
                       W + (size_t)(k0 + bkr + 8 * j) * N + n0 + bnc);
        }
        if (!ph) {
            float* ab = As + (size_t)buf * 128 * AP;
#pragma unroll
            for (int q = 0; q < 4; q++) {
                int r = ar + q * 32;
                int m = m0 + r;
                float* dst = ab + r * AP + ac4;
                if (m < N_NODES)
                    CP_ASYNC16((uint32_t)__cvta_generic_to_shared(dst),
                               A1 + (size_t)m * HID + k0 + ac4);
                else
                    *(float4*)dst = make_float4(0.f, 0.f, 0.f, 0.f);
            }
        } else {
#pragma unroll
            for (int q = 0; q < 4; q++) {
                int r = ar + q * 32;
                int m = m0 + r;
                float4 v = (m < N_NODES)
                               ? *(const float4*)(A2raw + (size_t)m * HID + k0 + ac4)
                               : make_float4(0.f, 0.f, 0.f, 0.f);
                float4 scv = *(const float4*)(g_scale + k0 + ac4);
                float4 shv = *(const float4*)(g_shift + k0 + ac4);
                v.x = fmaxf(v.x * scv.x + shv.x, 0.f);
                v.y = fmaxf(v.y * scv.y + shv.y, 0.f);
                v.z = fmaxf(v.z * scv.z + shv.z, 0.f);
                v.w = fmaxf(v.w * scv.w + shv.w, 0.f);
                sa[q] = v;
            }
        }
        CP_COMMIT();
    };

    issue(0);

#pragma unroll 1
    for (int i = 0; i < 16; i++) {
        int buf = i % 3;
        if (i >= 8) {
            float* ab = As + (size_t)buf * 128 * AP;
#pragma unroll
            for (int q = 0; q < 4; q++) {
                int r = ar + q * 32;
                float4 v;
                v.x = to_tf32(sa[q].x); v.y = to_tf32(sa[q].y);
                v.z = to_tf32(sa[q].z); v.w = to_tf32(sa[q].w);
                *(float4*)(ab + r * AP + ac4) = v;
            }
        }
        if (i + 1 < 16) {
            issue(i + 1);
            CP_WAIT(1);
        } else {
            CP_WAIT(0);
        }
        __syncthreads();
        const float* ab = As + (size_t)buf * 128 * AP;
        const float* bb = Bs + (size_t)buf * 32 * BP;
#pragma unroll
        for (int ks = 0; ks < 4; ks++) {
            int kb = ks * 8;
            uint32_t bf[4][2];
#pragma unroll
            for (int ni = 0; ni < 4; ni++) {
                int n = wn + ni * 8 + g;
                bf[ni][0] = __float_as_uint(bb[(kb + tig) * BP + n]);
                bf[ni][1] = __float_as_uint(bb[(kb + tig + 4) * BP + n]);
            }
#pragma unroll
            for (int mi = 0; mi < 4; mi++) {
                int m = wm + mi * 16 + g;
                uint32_t af[4];
                af[0] = __float_as_uint(ab[m * AP + kb + tig]);
                af[1] = __float_as_uint(ab[(m + 8) * AP + kb + tig]);
                af[2] = __float_as_uint(ab[m * AP + kb + tig + 4]);
                af[3] = __float_as_uint(ab[(m + 8) * AP + kb + tig + 4]);
#pragma unroll
                for (int ni = 0; ni < 4; ni++)
                    mma8(acc[mi][ni], af, bf[ni]);
            }
        }
    }

    // ---- epilogue: add bias, store, fused column stats ----
#pragma unroll
    for (int ni = 0; ni < 4; ni++) {
        int col = n0 + wn + ni * 8 + tig * 2;
        float b0 = bias[col], b1 = bias[col + 1];
        float s0 = 0.f, s1 = 0.f, q0 = 0.f, q1 = 0.f;
#pragma unroll
        for (int mi = 0; mi < 4; mi++) {
            int row0 = m0 + wm + mi * 16 + g;
            int row1 = row0 + 8;
            float v00 = acc[mi][ni][0] + b0, v01 = acc[mi][ni][1] + b1;
            float v10 = acc[mi][ni][2] + b0, v11 = acc[mi][ni][3] + b1;
            if (row0 < N_NODES) {
                *(float2*)(C + (size_t)row0 * N + col) = make_float2(v00, v01);
                s0 += v00; q0 += v00 * v00; s1 += v01; q1 += v01 * v01;
            }
            if (row1 < N_NODES) {
                *(float2*)(C + (size_t)row1 * N + col) = make_float2(v10, v11);
                s0 += v10; q0 += v10 * v10; s1 += v11; q1 += v11 * v11;
            }
        }
        if (doStats) {
#pragma unroll
            for (int off = 4; off < 32; off <<= 1) {
                s0 += __shfl_xor_sync(0xffffffffu, s0, off);
                s1 += __shfl_xor_sync(0xffffffffu, s1, off);
                q0 += __shfl_xor_sync(0xffffffffu, q0, off);
                q1 += __shfl_xor_sync(0xffffffffu, q1, off);
            }
            if (lane < 4) {
                atomicAdd(&g_stats[col], s0);
                atomicAdd(&g_stats[col + 1], s1);
                atomicAdd(&g_stats[HID + col], q0);
                atomicAdd(&g_stats[HID + col + 1], q1);
            }
        }
    }
}

// ---------------- orchestration ----------------------------------------------
extern "C" void kernel_launch(void* const* d_in, const int* in_sizes, int n_in,
                              void* d_out, int out_size) {
    const float* x    = (const float*)d_in[0];
    const int*   ei   = (const int*)d_in[1];
    const float* w_in = (const float*)d_in[2];
    const float* b_in = (const float*)d_in[3];
    const float* gi   = (const float*)d_in[4];
    const float* bei  = (const float*)d_in[5];
    const float* wl1  = (const float*)d_in[6];
    const float* bl1  = (const float*)d_in[7];
    const float* wr1  = (const float*)d_in[8];
    const float* g1   = (const float*)d_in[9];
    const float* be1  = (const float*)d_in[10];
    const float* wl2  = (const float*)d_in[11];
    const float* bl2  = (const float*)d_in[12];
    const float* wr2  = (const float*)d_in[13];
    const float* g2   = (const float*)d_in[14];
    const float* be2  = (const float*)d_in[15];
    const float* wl3  = (const float*)d_in[16];
    const float* bl3  = (const float*)d_in[17];
    const float* wr3  = (const float*)d_in[18];
    float* out = (float*)d_out;

    float *bufA, *bufB, *bufC, *rcnt, *wtf;
    int *deg, *rowstart, *cursor, *csrsrc, *bsum;
    cudaGetSymbolAddress((void**)&bufA, g_bufA);
    cudaGetSymbolAddress((void**)&bufB, g_bufB);
    cudaGetSymbolAddress((void**)&bufC, g_bufC);
    cudaGetSymbolAddress((void**)&rcnt, g_rcnt);
    cudaGetSymbolAddress((void**)&deg, g_deg);
    cudaGetSymbolAddress((void**)&rowstart, g_rowstart);
    cudaGetSymbolAddress((void**)&cursor, g_cursor);
    cudaGetSymbolAddress((void**)&csrsrc, g_csrsrc);
    cudaGetSymbolAddress((void**)&bsum, g_bsum);
    cudaGetSymbolAddress((void**)&wtf, g_wtf);

    const float* wl1t = wtf;
    const float* wr1t = wtf + 65536;
    const float* wl2t = wtf + 131072;
    const float* wr2t = wtf + 196608;
    const float* wl3t = wtf + 262144;
    const float* wr3t = wtf + 294912;

    cudaFuncSetAttribute(mma_dual_gemm,
                         cudaFuncAttributeMaxDynamicSharedMemorySize, SMEM_GEMM);

    // ---- CSR build + stats zero + weight pre-round ----
    zero_init<<<(N_NODES + 255) / 256, 256>>>(deg, rowstart);
    round_weights<<<327680 / 256, 256>>>(wl1, wr1, wl2, wr2, wl3, wr3);
    count_deg<<<(N_EDGES + 255) / 256, 256>>>(ei, deg);
    block_sums<<<SCAN_BLOCKS, 256>>>(deg, bsum);
    scan_emit<<<SCAN_BLOCKS, 256>>>(deg, bsum, rowstart, cursor, rcnt);
    fill_csr<<<(N_EDGES + 255) / 256, 256>>>(ei, cursor, csrsrc);

    // ---- input projection (fused stats) -> bufC raw; bn0 params ----
    input_proj<<<(N_NODES + 63) / 64, 256>>>(x, w_in, b_in, bufC);
    bn_finalize<<<1, HID>>>(gi, bei);

    const int MB = (N_NODES + 127) / 128;  // 391
    dim3 ggrid(MB, HID / 128);             // 391 x 2
    dim3 ogrid(MB, EMB / 128);             // 391 x 1
    const int AGG_BLOCKS = N_NODES / 4;    // 12500

    // ---- SAGE layer 1: raw=bufC (bn0 lazily) -> bufA raw; bn1 ----
    agg_gather_bn<<<AGG_BLOCKS, 256>>>(rowstart, csrsrc, rcnt, bufC, bufB);
    mma_dual_gemm<<<ggrid, 256, SMEM_GEMM>>>(bufB, bufC, wl1t, wr1t, bl1, bufA, HID, 1);
    bn_finalize<<<1, HID>>>(g1, be1);

    // ---- SAGE layer 2: raw=bufA -> bufC raw; bn2 ----
    agg_gather_bn<<<AGG_BLOCKS, 256>>>(rowstart, csrsrc, rcnt, bufA, bufB);
    mma_dual_gemm<<<ggrid, 256, SMEM_GEMM>>>(bufB, bufA, wl2t, wr2t, bl2, bufC, HID, 1);
    bn_finalize<<<1, HID>>>(g2, be2);

    // ---- SAGE layer 3: raw=bufC -> out (no BN) ----
    agg_gather_bn<<<AGG_BLOCKS, 256>>>(rowstart, csrsrc, rcnt, bufC, bufB);
    mma_dual_gemm<<<ogrid, 256, SMEM_GEMM>>>(bufB, bufC, wl3t, wr3t, bl3, out, EMB, 0);
}